// round 13
// baseline (speedup 1.0000x reference)
#include <cuda_runtime.h>
#include <cuda_fp16.h>
#include <cstdint>

// ---------------- problem constants ----------------
#define M_TOTAL 8192
#define K_TOTAL 4096
#define N_TOTAL 4096
#define RANK    16
#define SCALING 2.0f   // alpha/rank
#define QBLOCK  64

// ---------------- GEMM tile config ----------------
#define BM 128
#define BN 256
#define BK 64
#define STAGES 4
#define K_ITERS (K_TOTAL / BK)          // 64
#define OFF_X  0
#define OFF_W  (BM * BK * 2)            // 16384
#define STAGE_BYTES ((BM + BN) * BK * 2)   // 49152
#define SMEM_BYTES (STAGES * STAGE_BYTES)  // 196608

#define NTHREADS 256

// ---------------- scratch (device globals; no allocation allowed) ----------------
__device__ __align__(1024) __half g_xq[(size_t)M_TOTAL * K_TOTAL];   // fp16(x)
__device__ __align__(1024) __half g_w16[(size_t)N_TOTAL * K_TOTAL];  // fp16(s*(q-8))
__device__ __align__(1024) float  g_xa[(size_t)M_TOTAL * RANK];      // x @ lora_A

// ---------------- PTX helpers (sm_80-class only) ----------------
__device__ __forceinline__ uint32_t smem_u32(const void* p) {
    uint32_t a;
    asm("{ .reg .u64 t; cvta.to.shared.u64 t, %1; cvt.u32.u64 %0, t; }" : "=r"(a) : "l"(p));
    return a;
}
__device__ __forceinline__ void cp16(uint32_t dst, const void* src) {
    asm volatile("cp.async.cg.shared.global [%0], [%1], 16;" :: "r"(dst), "l"(src));
}
__device__ __forceinline__ void cp_commit() { asm volatile("cp.async.commit_group;"); }
template <int N>
__device__ __forceinline__ void cp_wait() { asm volatile("cp.async.wait_group %0;" :: "n"(N)); }

__device__ __forceinline__ void ldsm_x4(uint32_t (&r)[4], uint32_t addr) {
    asm volatile("ldmatrix.sync.aligned.m8n8.x4.shared.b16 {%0,%1,%2,%3}, [%4];"
                 : "=r"(r[0]), "=r"(r[1]), "=r"(r[2]), "=r"(r[3]) : "r"(addr));
}
__device__ __forceinline__ void mma16816(float (&d)[4], const uint32_t (&a)[4],
                                         uint32_t b0, uint32_t b1) {
    asm volatile(
        "mma.sync.aligned.m16n8k16.row.col.f32.f16.f16.f32 "
        "{%0,%1,%2,%3}, {%4,%5,%6,%7}, {%8,%9}, {%0,%1,%2,%3};"
        : "+f"(d[0]), "+f"(d[1]), "+f"(d[2]), "+f"(d[3])
        : "r"(a[0]), "r"(a[1]), "r"(a[2]), "r"(a[3]), "r"(b0), "r"(b1));
}

// smem tile: rows x 64 f16 (128 B/row = 8 x 16B chunks); xor-8 swizzle
__device__ __forceinline__ uint32_t tile_addr(uint32_t tbase, int row, int chunk) {
    return tbase + row * 128 + (((uint32_t)(chunk ^ (row & 7))) << 4);
}

// ---------------- prep kernels ----------------
// x -> fp16
__global__ void prep_x_kernel(const float* __restrict__ x) {
    size_t i = (size_t)blockIdx.x * blockDim.x + threadIdx.x;
    size_t n4 = (size_t)M_TOTAL * K_TOTAL / 4;
    if (i >= n4) return;
    float4 v = reinterpret_cast<const float4*>(x)[i];
    __half2* o2 = reinterpret_cast<__half2*>(g_xq);
    o2[2 * i + 0] = __floats2half2_rn(v.x, v.y);
    o2[2 * i + 1] = __floats2half2_rn(v.z, v.w);
}

// W16 = fp16( scale * (q-8) ); 16 elements per thread (one scale block slice)
__global__ void prep_w_kernel(const int* __restrict__ qw, const float* __restrict__ scales) {
    size_t i = (size_t)blockIdx.x * blockDim.x + threadIdx.x;   // 16 ints each
    size_t n16 = (size_t)N_TOTAL * K_TOTAL / 16;
    if (i >= n16) return;
    size_t e0 = i * 16;
    int o = (int)(e0 >> 12);            // /K_TOTAL
    int col = (int)(e0 & (K_TOTAL - 1));
    float s = __ldg(scales + (size_t)o * (K_TOTAL / QBLOCK) + (col >> 6));
    const int4* qp = reinterpret_cast<const int4*>(qw) + i * 4;
    __half2 h[8];
#pragma unroll
    for (int j = 0; j < 4; ++j) {
        int4 q = qp[j];
        h[2 * j + 0] = __floats2half2_rn(s * (float)(q.x - 8), s * (float)(q.y - 8));
        h[2 * j + 1] = __floats2half2_rn(s * (float)(q.z - 8), s * (float)(q.w - 8));
    }
    uint4* o4 = reinterpret_cast<uint4*>(g_w16) + i * 2;
    o4[0] = *reinterpret_cast<uint4*>(&h[0]);
    o4[1] = *reinterpret_cast<uint4*>(&h[4]);
}

// xa = x @ lora_A  (8192x16) — latency-tolerant (R9 version)
__global__ void __launch_bounds__(256, 4)
prep_xa_kernel(const float* __restrict__ x, const float* __restrict__ A) {
    __shared__ float As[8192];
    const int tid = threadIdx.x;
    const int row = tid & 31;
    const int kq  = tid >> 5;
    const int m0 = blockIdx.x * 32;

    float acc[16];
#pragma unroll
    for (int r = 0; r < 16; ++r) acc[r] = 0.0f;

    for (int t = 0; t < 8; ++t) {
        __syncthreads();
#pragma unroll
        for (int j = 0; j < 8; ++j) {
            int f = tid + 256 * j;
            reinterpret_cast<float4*>(As)[f] =
                reinterpret_cast<const float4*>(A + (size_t)t * 512 * RANK)[f];
        }
        __syncthreads();

        const float4* xr = reinterpret_cast<const float4*>(
            x + (size_t)(m0 + row) * K_TOTAL + t * 512 + kq * 64);
        const float* Ak = As + kq * 64 * RANK;
#pragma unroll 4
        for (int j = 0; j < 16; ++j) {
            float4 xv = xr[j];
            float xs4[4] = {xv.x, xv.y, xv.z, xv.w};
#pragma unroll
            for (int kk = 0; kk < 4; ++kk) {
                float xs = xs4[kk];
                const float4* ar =
                    reinterpret_cast<const float4*>(Ak + (j * 4 + kk) * RANK);
#pragma unroll
                for (int rq = 0; rq < 4; ++rq) {
                    float4 av = ar[rq];
                    acc[rq * 4 + 0] = fmaf(xs, av.x, acc[rq * 4 + 0]);
                    acc[rq * 4 + 1] = fmaf(xs, av.y, acc[rq * 4 + 1]);
                    acc[rq * 4 + 2] = fmaf(xs, av.z, acc[rq * 4 + 2]);
                    acc[rq * 4 + 3] = fmaf(xs, av.w, acc[rq * 4 + 3]);
                }
            }
        }
    }

    __syncthreads();
#pragma unroll
    for (int r = 0; r < 16; ++r) As[kq * 544 + row * 17 + r] = acc[r];
    __syncthreads();
#pragma unroll
    for (int u = 0; u < 2; ++u) {
        int o = tid * 2 + u;
        int ro = o >> 4, rr = o & 15;
        float s = 0.0f;
#pragma unroll
        for (int q = 0; q < 8; ++q) s += As[q * 544 + ro * 17 + rr];
        g_xa[(size_t)(m0 + ro) * RANK + rr] = s;
    }
}

// ---------------- main GEMM: fp16, 8 warps, 64x64 warp tiles, CTA 128x256 -------
__global__ void __launch_bounds__(NTHREADS, 1)
gemm_kernel(const float* __restrict__ bias, const float* __restrict__ loraB,
            float* __restrict__ out) {
    extern __shared__ __align__(1024) char smem[];
    uint32_t sb = smem_u32(smem);
    const int tid = threadIdx.x;
    const int lane = tid & 31;
    const int wid = tid >> 5;
    const int warp_m = wid & 1;    // 0..1 (64 rows each)
    const int warp_n = wid >> 1;   // 0..3 (64 cols each)

    // block swizzle for L2 reuse
    const int tiles_n = N_TOTAL / BN;   // 16
    const int GM = 8;
    int bid = blockIdx.x;
    int group = bid / (GM * tiles_n);
    int mt_idx = group * GM + (bid % GM);
    int nt_idx = (bid % (GM * tiles_n)) / GM;
    const int m0 = mt_idx * BM;
    const int n0 = nt_idx * BN;

    auto load_stage = [&](int s, int it) {
        const int k0 = it * BK;
        uint32_t stb = sb + s * STAGE_BYTES;
#pragma unroll
        for (int j = 0; j < 4; ++j) {          // X: 1024 chunks
            int idx = tid + NTHREADS * j;
            int row = idx >> 3;
            int chk = idx & 7;
            cp16(tile_addr(stb + OFF_X, row, chk),
                 g_xq + (size_t)(m0 + row) * K_TOTAL + k0 + chk * 8);
        }
#pragma unroll
        for (int j = 0; j < 8; ++j) {          // W: 2048 chunks
            int idx = tid + NTHREADS * j;
            int row = idx >> 3;
            int chk = idx & 7;
            cp16(tile_addr(stb + OFF_W, row, chk),
                 g_w16 + (size_t)(n0 + row) * K_TOTAL + k0 + chk * 8);
        }
    };

#pragma unroll
    for (int s = 0; s < STAGES - 1; ++s) {
        load_stage(s, s);
        cp_commit();
    }

    float acc[4][8][4];
#pragma unroll
    for (int a = 0; a < 4; ++a)
#pragma unroll
        for (int b = 0; b < 8; ++b)
#pragma unroll
            for (int c = 0; c < 4; ++c) acc[a][b][c] = 0.0f;

    // A frags (non-trans): {m0-7,klo},{m8-15,klo},{m0-7,khi},{m8-15,khi}
    const int a_row_l = lane & 15;
    const int a_chk_l = lane >> 4;
    // B frags (non-trans, W rows = n): {n0-7,klo},{n0-7,khi},{n8-15,klo},{n8-15,khi}
    const int b_row_l = ((lane >> 4) << 3) + (lane & 7);
    const int b_chk_l = (lane >> 3) & 1;
    const int tr = lane >> 2;
    const int tc = (lane & 3) * 2;

    for (int it = 0; it < K_ITERS; ++it) {
        cp_wait<STAGES - 2>();
        __syncthreads();

        int nxt = it + STAGES - 1;
        if (nxt < K_ITERS) load_stage(nxt % STAGES, nxt);
        cp_commit();

        uint32_t stb = sb + (it % STAGES) * STAGE_BYTES;

#pragma unroll
        for (int kk = 0; kk < 4; ++kk) {
            uint32_t a[4][4], bq[4][4];
#pragma unroll
            for (int mt = 0; mt < 4; ++mt) {
                int row = warp_m * 64 + mt * 16 + a_row_l;
                ldsm_x4(a[mt], tile_addr(stb + OFF_X, row, kk * 2 + a_chk_l));
            }
#pragma unroll
            for (int nb = 0; nb < 4; ++nb) {
                int row = warp_n * 64 + nb * 16 + b_row_l;
                ldsm_x4(bq[nb], tile_addr(stb + OFF_W, row, kk * 2 + b_chk_l));
            }
#pragma unroll
            for (int mt = 0; mt < 4; ++mt)
#pragma unroll
                for (int nt = 0; nt < 8; ++nt) {
                    const int nb = nt >> 1;
                    const int hi = (nt & 1) * 2;
                    mma16816(acc[mt][nt], a[mt], bq[nb][hi], bq[nb][hi + 1]);
                }
        }
    }

    // ---- epilogue: LoRA (rank-16) + bias, then store ----
    cp_wait<0>();
    __syncthreads();
    float* xa_s = reinterpret_cast<float*>(smem);                // [128][17]
    float* bl_s = reinterpret_cast<float*>(smem + 128 * 17 * 4); // [16][256]
#pragma unroll
    for (int j = 0; j < 8; ++j) {
        int idx = tid + NTHREADS * j;      // 0..2047
        int row = idx >> 4, r = idx & 15;
        xa_s[row * 17 + r] = g_xa[(size_t)(m0 + row) * RANK + r];
    }
#pragma unroll
    for (int j = 0; j < 16; ++j) {
        int idx = tid + NTHREADS * j;      // 0..4095
        int rr = idx >> 8, col = idx & 255;
        bl_s[rr * 256 + col] = SCALING * loraB[(size_t)rr * N_TOTAL + n0 + col];
    }
    __syncthreads();

#pragma unroll
    for (int r = 0; r < RANK; ++r) {
        float xv[8];
#pragma unroll
        for (int mt = 0; mt < 4; ++mt) {
            int rowl = warp_m * 64 + mt * 16 + tr;
            xv[2 * mt]     = xa_s[rowl * 17 + r];
            xv[2 * mt + 1] = xa_s[(rowl + 8) * 17 + r];
        }
#pragma unroll
        for (int nt = 0; nt < 8; ++nt) {
            float2 bv = *reinterpret_cast<const float2*>(
                &bl_s[r * 256 + warp_n * 64 + nt * 8 + tc]);
#pragma unroll
            for (int mt = 0; mt < 4; ++mt) {
                acc[mt][nt][0] = fmaf(xv[2 * mt],     bv.x, acc[mt][nt][0]);
                acc[mt][nt][1] = fmaf(xv[2 * mt],     bv.y, acc[mt][nt][1]);
                acc[mt][nt][2] = fmaf(xv[2 * mt + 1], bv.x, acc[mt][nt][2]);
                acc[mt][nt][3] = fmaf(xv[2 * mt + 1], bv.y, acc[mt][nt][3]);
            }
        }
    }

#pragma unroll
    for (int nt = 0; nt < 8; ++nt) {
        int n = n0 + warp_n * 64 + nt * 8 + tc;
        float2 bv = *reinterpret_cast<const float2*>(bias + n);
#pragma unroll
        for (int mt = 0; mt < 4; ++mt) {
            int m = m0 + warp_m * 64 + mt * 16 + tr;
            float2 v0 = make_float2(acc[mt][nt][0] + bv.x, acc[mt][nt][1] + bv.y);
            float2 v1 = make_float2(acc[mt][nt][2] + bv.x, acc[mt][nt][3] + bv.y);
            *reinterpret_cast<float2*>(out + (size_t)m * N_TOTAL + n) = v0;
            *reinterpret_cast<float2*>(out + (size_t)(m + 8) * N_TOTAL + n) = v1;
        }
    }
}

// ---------------- host launch ----------------
extern "C" void kernel_launch(void* const* d_in, const int* in_sizes, int n_in,
                              void* d_out, int out_size) {
    const float* x      = (const float*)d_in[0];
    const int*   qw     = (const int*)d_in[1];
    const float* scales = (const float*)d_in[2];
    const float* bias   = (const float*)d_in[3];
    const float* lora_A = (const float*)d_in[4];
    const float* lora_B = (const float*)d_in[5];
    float* out = (float*)d_out;

    {
        size_t n4 = (size_t)M_TOTAL * K_TOTAL / 4;
        prep_x_kernel<<<(unsigned)((n4 + 255) / 256), 256>>>(x);
        size_t w16 = (size_t)N_TOTAL * K_TOTAL / 16;
        prep_w_kernel<<<(unsigned)((w16 + 255) / 256), 256>>>(qw, scales);
        prep_xa_kernel<<<M_TOTAL / 32, 256>>>(x, lora_A);
    }

    cudaFuncSetAttribute(gemm_kernel, cudaFuncAttributeMaxDynamicSharedMemorySize,
                         SMEM_BYTES);
    int grid = (M_TOTAL / BM) * (N_TOTAL / BN);   // 1024
    gemm_kernel<<<grid, NTHREADS, SMEM_BYTES>>>(bias, lora_B, out);
}

// round 14
// speedup vs baseline: 1.6051x; 1.6051x over previous
#include <cuda_runtime.h>
#include <cuda_fp16.h>
#include <cstdint>

// ---------------- problem constants ----------------
#define M_TOTAL 8192
#define K_TOTAL 4096
#define N_TOTAL 4096
#define RANK    16
#define SCALING 2.0f   // alpha/rank
#define QBLOCK  64

// ---------------- GEMM tile config ----------------
#define BM 128
#define BN 128
#define BK 64
#define STAGES 3
#define K_ITERS (K_TOTAL / BK)          // 64
#define OFF_X  0
#define OFF_W  (BM * BK * 2)            // 16384
#define STAGE_BYTES ((BM + BN) * BK * 2)   // 32768
#define SMEM_BYTES (STAGES * STAGE_BYTES)  // 98304

#define NTHREADS 256

// ---------------- scratch (device globals; no allocation allowed) ----------------
__device__ __align__(1024) __half g_xq[(size_t)M_TOTAL * K_TOTAL];   // fp16(x)
__device__ __align__(1024) __half g_w16[(size_t)N_TOTAL * K_TOTAL];  // fp16(s*(q-8))
__device__ __align__(1024) float  g_xa[(size_t)M_TOTAL * RANK];      // x @ lora_A

// ---------------- PTX helpers (sm_80-class only) ----------------
__device__ __forceinline__ uint32_t smem_u32(const void* p) {
    uint32_t a;
    asm("{ .reg .u64 t; cvta.to.shared.u64 t, %1; cvt.u32.u64 %0, t; }" : "=r"(a) : "l"(p));
    return a;
}
__device__ __forceinline__ void cp16(uint32_t dst, const void* src) {
    asm volatile("cp.async.cg.shared.global [%0], [%1], 16;" :: "r"(dst), "l"(src));
}
__device__ __forceinline__ void cp_commit() { asm volatile("cp.async.commit_group;"); }
template <int N>
__device__ __forceinline__ void cp_wait() { asm volatile("cp.async.wait_group %0;" :: "n"(N)); }

__device__ __forceinline__ void ldsm_x4(uint32_t (&r)[4], uint32_t addr) {
    asm volatile("ldmatrix.sync.aligned.m8n8.x4.shared.b16 {%0,%1,%2,%3}, [%4];"
                 : "=r"(r[0]), "=r"(r[1]), "=r"(r[2]), "=r"(r[3]) : "r"(addr));
}
__device__ __forceinline__ void mma16816(float (&d)[4], const uint32_t (&a)[4],
                                         uint32_t b0, uint32_t b1) {
    asm volatile(
        "mma.sync.aligned.m16n8k16.row.col.f32.f16.f16.f32 "
        "{%0,%1,%2,%3}, {%4,%5,%6,%7}, {%8,%9}, {%0,%1,%2,%3};"
        : "+f"(d[0]), "+f"(d[1]), "+f"(d[2]), "+f"(d[3])
        : "r"(a[0]), "r"(a[1]), "r"(a[2]), "r"(a[3]), "r"(b0), "r"(b1));
}

// smem tile: rows x 64 f16 (128 B/row = 8 x 16B chunks); xor-8 swizzle
__device__ __forceinline__ uint32_t tile_addr(uint32_t tbase, int row, int chunk) {
    return tbase + row * 128 + (((uint32_t)(chunk ^ (row & 7))) << 4);
}

// ---------------- prep kernels ----------------
// x -> fp16
__global__ void prep_x_kernel(const float* __restrict__ x) {
    size_t i = (size_t)blockIdx.x * blockDim.x + threadIdx.x;
    size_t n4 = (size_t)M_TOTAL * K_TOTAL / 4;
    if (i >= n4) return;
    float4 v = reinterpret_cast<const float4*>(x)[i];
    __half2* o2 = reinterpret_cast<__half2*>(g_xq);
    o2[2 * i + 0] = __floats2half2_rn(v.x, v.y);
    o2[2 * i + 1] = __floats2half2_rn(v.z, v.w);
}

// W16 = fp16( scale * (q-8) ); 16 elements per thread (one scale block slice)
__global__ void prep_w_kernel(const int* __restrict__ qw, const float* __restrict__ scales) {
    size_t i = (size_t)blockIdx.x * blockDim.x + threadIdx.x;   // 16 ints each
    size_t n16 = (size_t)N_TOTAL * K_TOTAL / 16;
    if (i >= n16) return;
    size_t e0 = i * 16;
    int o = (int)(e0 >> 12);            // /K_TOTAL
    int col = (int)(e0 & (K_TOTAL - 1));
    float s = __ldg(scales + (size_t)o * (K_TOTAL / QBLOCK) + (col >> 6));
    const int4* qp = reinterpret_cast<const int4*>(qw) + i * 4;
    __half2 h[8];
#pragma unroll
    for (int j = 0; j < 4; ++j) {
        int4 q = qp[j];
        h[2 * j + 0] = __floats2half2_rn(s * (float)(q.x - 8), s * (float)(q.y - 8));
        h[2 * j + 1] = __floats2half2_rn(s * (float)(q.z - 8), s * (float)(q.w - 8));
    }
    uint4* o4 = reinterpret_cast<uint4*>(g_w16) + i * 2;
    o4[0] = *reinterpret_cast<uint4*>(&h[0]);
    o4[1] = *reinterpret_cast<uint4*>(&h[4]);
}

// xa = x @ lora_A  (8192x16) — latency-tolerant
__global__ void __launch_bounds__(256, 4)
prep_xa_kernel(const float* __restrict__ x, const float* __restrict__ A) {
    __shared__ float As[8192];
    const int tid = threadIdx.x;
    const int row = tid & 31;
    const int kq  = tid >> 5;
    const int m0 = blockIdx.x * 32;

    float acc[16];
#pragma unroll
    for (int r = 0; r < 16; ++r) acc[r] = 0.0f;

    for (int t = 0; t < 8; ++t) {
        __syncthreads();
#pragma unroll
        for (int j = 0; j < 8; ++j) {
            int f = tid + 256 * j;
            reinterpret_cast<float4*>(As)[f] =
                reinterpret_cast<const float4*>(A + (size_t)t * 512 * RANK)[f];
        }
        __syncthreads();

        const float4* xr = reinterpret_cast<const float4*>(
            x + (size_t)(m0 + row) * K_TOTAL + t * 512 + kq * 64);
        const float* Ak = As + kq * 64 * RANK;
#pragma unroll 4
        for (int j = 0; j < 16; ++j) {
            float4 xv = xr[j];
            float xs4[4] = {xv.x, xv.y, xv.z, xv.w};
#pragma unroll
            for (int kk = 0; kk < 4; ++kk) {
                float xs = xs4[kk];
                const float4* ar =
                    reinterpret_cast<const float4*>(Ak + (j * 4 + kk) * RANK);
#pragma unroll
                for (int rq = 0; rq < 4; ++rq) {
                    float4 av = ar[rq];
                    acc[rq * 4 + 0] = fmaf(xs, av.x, acc[rq * 4 + 0]);
                    acc[rq * 4 + 1] = fmaf(xs, av.y, acc[rq * 4 + 1]);
                    acc[rq * 4 + 2] = fmaf(xs, av.z, acc[rq * 4 + 2]);
                    acc[rq * 4 + 3] = fmaf(xs, av.w, acc[rq * 4 + 3]);
                }
            }
        }
    }

    __syncthreads();
#pragma unroll
    for (int r = 0; r < 16; ++r) As[kq * 544 + row * 17 + r] = acc[r];
    __syncthreads();
#pragma unroll
    for (int u = 0; u < 2; ++u) {
        int o = tid * 2 + u;
        int ro = o >> 4, rr = o & 15;
        float s = 0.0f;
#pragma unroll
        for (int q = 0; q < 8; ++q) s += As[q * 544 + ro * 17 + rr];
        g_xa[(size_t)(m0 + ro) * RANK + rr] = s;
    }
}

// ---------------- main GEMM: fp16 prefolded W, 8 warps 64x32 tiles, 2 CTAs/SM ---
__global__ void __launch_bounds__(NTHREADS, 2)
gemm_kernel(const float* __restrict__ bias, const float* __restrict__ loraB,
            float* __restrict__ out) {
    extern __shared__ __align__(1024) char smem[];
    uint32_t sb = smem_u32(smem);
    const int tid = threadIdx.x;
    const int lane = tid & 31;
    const int wid = tid >> 5;
    const int warp_m = wid >> 2;   // 0..1 (64 rows each)
    const int warp_n = wid & 3;    // 0..3 (32 cols each)

    // block swizzle for L2 reuse
    const int tiles_n = N_TOTAL / BN;   // 32
    const int GM = 8;
    int bid = blockIdx.x;
    int group = bid / (GM * tiles_n);
    int mt_idx = group * GM + (bid % GM);
    int nt_idx = (bid % (GM * tiles_n)) / GM;
    const int m0 = mt_idx * BM;
    const int n0 = nt_idx * BN;

    auto load_stage = [&](int s, int it) {
        const int k0 = it * BK;
        uint32_t stb = sb + s * STAGE_BYTES;
#pragma unroll
        for (int j = 0; j < 4; ++j) {
            int idx = tid + NTHREADS * j;   // 0..1023
            int row = idx >> 3;
            int chk = idx & 7;
            cp16(tile_addr(stb + OFF_X, row, chk),
                 g_xq + (size_t)(m0 + row) * K_TOTAL + k0 + chk * 8);
            cp16(tile_addr(stb + OFF_W, row, chk),
                 g_w16 + (size_t)(n0 + row) * K_TOTAL + k0 + chk * 8);
        }
    };

#pragma unroll
    for (int s = 0; s < STAGES - 1; ++s) {
        load_stage(s, s);
        cp_commit();
    }

    float acc[4][4][4];
#pragma unroll
    for (int a = 0; a < 4; ++a)
#pragma unroll
        for (int b = 0; b < 4; ++b)
#pragma unroll
            for (int c = 0; c < 4; ++c) acc[a][b][c] = 0.0f;

    // A frags (non-trans): {m0-7,klo},{m8-15,klo},{m0-7,khi},{m8-15,khi}
    const int a_row_l = lane & 15;
    const int a_chk_l = lane >> 4;
    // B frags (non-trans, W rows = n): {n0-7,klo},{n0-7,khi},{n8-15,klo},{n8-15,khi}
    const int b_row_l = ((lane >> 4) << 3) + (lane & 7);
    const int b_chk_l = (lane >> 3) & 1;
    const int tr = lane >> 2;
    const int tc = (lane & 3) * 2;

    for (int it = 0; it < K_ITERS; ++it) {
        cp_wait<STAGES - 2>();
        __syncthreads();

        int nxt = it + STAGES - 1;
        if (nxt < K_ITERS) load_stage(nxt % STAGES, nxt);
        cp_commit();

        uint32_t stb = sb + (it % STAGES) * STAGE_BYTES;

#pragma unroll
        for (int kk = 0; kk < 4; ++kk) {
            uint32_t a[4][4], bq[2][4];
#pragma unroll
            for (int mt = 0; mt < 4; ++mt) {
                int row = warp_m * 64 + mt * 16 + a_row_l;
                ldsm_x4(a[mt], tile_addr(stb + OFF_X, row, kk * 2 + a_chk_l));
            }
#pragma unroll
            for (int nb = 0; nb < 2; ++nb) {
                int row = warp_n * 32 + nb * 16 + b_row_l;
                ldsm_x4(bq[nb], tile_addr(stb + OFF_W, row, kk * 2 + b_chk_l));
            }
#pragma unroll
            for (int mt = 0; mt < 4; ++mt)
#pragma unroll
                for (int nt = 0; nt < 4; ++nt) {
                    const int nb = nt >> 1;
                    const int hi = (nt & 1) * 2;
                    mma16816(acc[mt][nt], a[mt], bq[nb][hi], bq[nb][hi + 1]);
                }
        }
    }

    // ---- epilogue: LoRA (rank-16) + bias, then store ----
    cp_wait<0>();
    __syncthreads();
    float* xa_s = reinterpret_cast<float*>(smem);                // [128][17]
    float* bl_s = reinterpret_cast<float*>(smem + 128 * 17 * 4); // [16][128]
#pragma unroll
    for (int j = 0; j < 8; ++j) {
        int idx = tid + NTHREADS * j;      // 0..2047
        int row = idx >> 4, r = idx & 15;
        xa_s[row * 17 + r] = g_xa[(size_t)(m0 + row) * RANK + r];
        int rr = idx >> 7, col = idx & 127;
        bl_s[rr * 128 + col] = SCALING * loraB[(size_t)rr * N_TOTAL + n0 + col];
    }
    __syncthreads();

#pragma unroll
    for (int r = 0; r < RANK; ++r) {
        float xv[8];
#pragma unroll
        for (int mt = 0; mt < 4; ++mt) {
            int rowl = warp_m * 64 + mt * 16 + tr;
            xv[2 * mt]     = xa_s[rowl * 17 + r];
            xv[2 * mt + 1] = xa_s[(rowl + 8) * 17 + r];
        }
#pragma unroll
        for (int nt = 0; nt < 4; ++nt) {
            float2 bv = *reinterpret_cast<const float2*>(
                &bl_s[r * 128 + warp_n * 32 + nt * 8 + tc]);
#pragma unroll
            for (int mt = 0; mt < 4; ++mt) {
                acc[mt][nt][0] = fmaf(xv[2 * mt],     bv.x, acc[mt][nt][0]);
                acc[mt][nt][1] = fmaf(xv[2 * mt],     bv.y, acc[mt][nt][1]);
                acc[mt][nt][2] = fmaf(xv[2 * mt + 1], bv.x, acc[mt][nt][2]);
                acc[mt][nt][3] = fmaf(xv[2 * mt + 1], bv.y, acc[mt][nt][3]);
            }
        }
    }

#pragma unroll
    for (int nt = 0; nt < 4; ++nt) {
        int n = n0 + warp_n * 32 + nt * 8 + tc;
        float2 bv = *reinterpret_cast<const float2*>(bias + n);
#pragma unroll
        for (int mt = 0; mt < 4; ++mt) {
            int m = m0 + warp_m * 64 + mt * 16 + tr;
            float2 v0 = make_float2(acc[mt][nt][0] + bv.x, acc[mt][nt][1] + bv.y);
            float2 v1 = make_float2(acc[mt][nt][2] + bv.x, acc[mt][nt][3] + bv.y);
            *reinterpret_cast<float2*>(out + (size_t)m * N_TOTAL + n) = v0;
            *reinterpret_cast<float2*>(out + (size_t)(m + 8) * N_TOTAL + n) = v1;
        }
    }
}

// ---------------- host launch ----------------
extern "C" void kernel_launch(void* const* d_in, const int* in_sizes, int n_in,
                              void* d_out, int out_size) {
    const float* x      = (const float*)d_in[0];
    const int*   qw     = (const int*)d_in[1];
    const float* scales = (const float*)d_in[2];
    const float* bias   = (const float*)d_in[3];
    const float* lora_A = (const float*)d_in[4];
    const float* lora_B = (const float*)d_in[5];
    float* out = (float*)d_out;

    {
        size_t n4 = (size_t)M_TOTAL * K_TOTAL / 4;
        prep_x_kernel<<<(unsigned)((n4 + 255) / 256), 256>>>(x);
        size_t w16 = (size_t)N_TOTAL * K_TOTAL / 16;
        prep_w_kernel<<<(unsigned)((w16 + 255) / 256), 256>>>(qw, scales);
        prep_xa_kernel<<<M_TOTAL / 32, 256>>>(x, lora_A);
    }

    cudaFuncSetAttribute(gemm_kernel, cudaFuncAttributeMaxDynamicSharedMemorySize,
                         SMEM_BYTES);
    int grid = (M_TOTAL / BM) * (N_TOTAL / BN);   // 2048
    gemm_kernel<<<grid, NTHREADS, SMEM_BYTES>>>(bias, lora_B, out);
}

// round 16
// speedup vs baseline: 1.6714x; 1.0413x over previous
#include <cuda_runtime.h>
#include <cuda_fp16.h>
#include <cstdint>

// ---------------- problem constants ----------------
#define M_TOTAL 8192
#define K_TOTAL 4096
#define N_TOTAL 4096
#define RANK    16
#define SCALING 2.0f   // alpha/rank
#define QBLOCK  64

// ---------------- GEMM tile config ----------------
#define BM 128
#define BN 128
#define BK 64
#define STAGES 3
#define K_ITERS (K_TOTAL / BK)          // 64
#define OFF_X  0
#define OFF_W  (BM * BK * 2)            // 16384
#define STAGE_BYTES ((BM + BN) * BK * 2)   // 32768
#define SMEM_BYTES (STAGES * STAGE_BYTES)  // 98304

#define NTHREADS 256

// ---------------- scratch (device globals; no allocation allowed) ----------------
__device__ __align__(1024) __half g_xq[(size_t)M_TOTAL * K_TOTAL];   // fp16(x)
__device__ __align__(1024) __half g_w16[(size_t)N_TOTAL * K_TOTAL];  // fp16(s*(q-8))
__device__ __align__(1024) float  g_xa[(size_t)M_TOTAL * RANK];      // x @ lora_A

// ---------------- PTX helpers (sm_80-class only) ----------------
__device__ __forceinline__ uint32_t smem_u32(const void* p) {
    uint32_t a;
    asm("{ .reg .u64 t; cvta.to.shared.u64 t, %1; cvt.u32.u64 %0, t; }" : "=r"(a) : "l"(p));
    return a;
}
__device__ __forceinline__ void cp16(uint32_t dst, const void* src) {
    asm volatile("cp.async.cg.shared.global [%0], [%1], 16;" :: "r"(dst), "l"(src));
}
__device__ __forceinline__ void cp_commit() { asm volatile("cp.async.commit_group;"); }
template <int N>
__device__ __forceinline__ void cp_wait() { asm volatile("cp.async.wait_group %0;" :: "n"(N)); }

__device__ __forceinline__ void ldsm_x4(uint32_t (&r)[4], uint32_t addr) {
    asm volatile("ldmatrix.sync.aligned.m8n8.x4.shared.b16 {%0,%1,%2,%3}, [%4];"
                 : "=r"(r[0]), "=r"(r[1]), "=r"(r[2]), "=r"(r[3]) : "r"(addr));
}
__device__ __forceinline__ void mma16816(float (&d)[4], const uint32_t (&a)[4],
                                         uint32_t b0, uint32_t b1) {
    asm volatile(
        "mma.sync.aligned.m16n8k16.row.col.f32.f16.f16.f32 "
        "{%0,%1,%2,%3}, {%4,%5,%6,%7}, {%8,%9}, {%0,%1,%2,%3};"
        : "+f"(d[0]), "+f"(d[1]), "+f"(d[2]), "+f"(d[3])
        : "r"(a[0]), "r"(a[1]), "r"(a[2]), "r"(a[3]), "r"(b0), "r"(b1));
}

// smem tile: rows x 64 f16 (128 B/row = 8 x 16B chunks); xor-8 swizzle
__device__ __forceinline__ uint32_t tile_addr(uint32_t tbase, int row, int chunk) {
    return tbase + row * 128 + (((uint32_t)(chunk ^ (row & 7))) << 4);
}

// ---------------- prep kernels ----------------
// W16 = fp16( scale * (q-8) ); 16 elements per thread (one scale block slice)
__global__ void prep_w_kernel(const int* __restrict__ qw, const float* __restrict__ scales) {
    size_t i = (size_t)blockIdx.x * blockDim.x + threadIdx.x;   // 16 ints each
    size_t n16 = (size_t)N_TOTAL * K_TOTAL / 16;
    if (i >= n16) return;
    size_t e0 = i * 16;
    int o = (int)(e0 >> 12);            // /K_TOTAL
    int col = (int)(e0 & (K_TOTAL - 1));
    float s = __ldg(scales + (size_t)o * (K_TOTAL / QBLOCK) + (col >> 6));
    const int4* qp = reinterpret_cast<const int4*>(qw) + i * 4;
    __half2 h[8];
#pragma unroll
    for (int j = 0; j < 4; ++j) {
        int4 q = qp[j];
        h[2 * j + 0] = __floats2half2_rn(s * (float)(q.x - 8), s * (float)(q.y - 8));
        h[2 * j + 1] = __floats2half2_rn(s * (float)(q.z - 8), s * (float)(q.w - 8));
    }
    uint4* o4 = reinterpret_cast<uint4*>(g_w16) + i * 2;
    o4[0] = *reinterpret_cast<uint4*>(&h[0]);
    o4[1] = *reinterpret_cast<uint4*>(&h[4]);
}

// Fused: g_xq = fp16(x)  AND  xa = x @ lora_A  in ONE pass over x.
// Block: 32 rows x 8 k-slices (256 thr). A staged in smem; 16 rank accumulators.
__global__ void __launch_bounds__(256, 4)
prep_x_xa_kernel(const float* __restrict__ x, const float* __restrict__ A) {
    __shared__ float As[8192];   // 512x16 A tile; reused as reduction buffer
    const int tid = threadIdx.x;
    const int row = tid & 31;
    const int kq  = tid >> 5;
    const int m0 = blockIdx.x * 32;

    float acc[16];
#pragma unroll
    for (int r = 0; r < 16; ++r) acc[r] = 0.0f;

    for (int t = 0; t < 8; ++t) {
        __syncthreads();
#pragma unroll
        for (int j = 0; j < 8; ++j) {
            int f = tid + 256 * j;
            reinterpret_cast<float4*>(As)[f] =
                reinterpret_cast<const float4*>(A + (size_t)t * 512 * RANK)[f];
        }
        __syncthreads();

        const size_t xoff = (size_t)(m0 + row) * K_TOTAL + t * 512 + kq * 64;
        const float4* xr = reinterpret_cast<const float4*>(x + xoff);
        uint2* xq2 = reinterpret_cast<uint2*>(g_xq + xoff);
        const float* Ak = As + kq * 64 * RANK;
#pragma unroll 4
        for (int j = 0; j < 16; ++j) {
            float4 xv = xr[j];
            // write fp16 copy (8 bytes: 4 halves)
            __half2 h0 = __floats2half2_rn(xv.x, xv.y);
            __half2 h1 = __floats2half2_rn(xv.z, xv.w);
            uint2 hw;
            hw.x = *reinterpret_cast<uint32_t*>(&h0);
            hw.y = *reinterpret_cast<uint32_t*>(&h1);
            xq2[j] = hw;
            float xs4[4] = {xv.x, xv.y, xv.z, xv.w};
#pragma unroll
            for (int kk = 0; kk < 4; ++kk) {
                float xs = xs4[kk];
                const float4* ar =
                    reinterpret_cast<const float4*>(Ak + (j * 4 + kk) * RANK);
#pragma unroll
                for (int rq = 0; rq < 4; ++rq) {
                    float4 av = ar[rq];
                    acc[rq * 4 + 0] = fmaf(xs, av.x, acc[rq * 4 + 0]);
                    acc[rq * 4 + 1] = fmaf(xs, av.y, acc[rq * 4 + 1]);
                    acc[rq * 4 + 2] = fmaf(xs, av.z, acc[rq * 4 + 2]);
                    acc[rq * 4 + 3] = fmaf(xs, av.w, acc[rq * 4 + 3]);
                }
            }
        }
    }

    __syncthreads();
#pragma unroll
    for (int r = 0; r < 16; ++r) As[kq * 544 + row * 17 + r] = acc[r];
    __syncthreads();
#pragma unroll
    for (int u = 0; u < 2; ++u) {
        int o = tid * 2 + u;
        int ro = o >> 4, rr = o & 15;
        float s = 0.0f;
#pragma unroll
        for (int q = 0; q < 8; ++q) s += As[q * 544 + ro * 17 + rr];
        g_xa[(size_t)(m0 + ro) * RANK + rr] = s;
    }
}

// ---------------- main GEMM: fp16 prefolded W, 8 warps 64x32 tiles, 2 CTAs/SM ---
__global__ void __launch_bounds__(NTHREADS, 2)
gemm_kernel(const float* __restrict__ bias, const float* __restrict__ loraB,
            float* __restrict__ out) {
    extern __shared__ __align__(1024) char smem[];
    uint32_t sb = smem_u32(smem);
    const int tid = threadIdx.x;
    const int lane = tid & 31;
    const int wid = tid >> 5;
    const int warp_m = wid >> 2;   // 0..1 (64 rows each)
    const int warp_n = wid & 3;    // 0..3 (32 cols each)

    // block swizzle for L2 reuse
    const int tiles_n = N_TOTAL / BN;   // 32
    const int GM = 8;
    int bid = blockIdx.x;
    int group = bid / (GM * tiles_n);
    int mt_idx = group * GM + (bid % GM);
    int nt_idx = (bid % (GM * tiles_n)) / GM;
    const int m0 = mt_idx * BM;
    const int n0 = nt_idx * BN;

    // ---- strength-reduced cp.async addressing ----
    // j-row stride is 32 (== 0 mod 8) -> swizzled chunk is j-invariant.
    const int ld_row = tid >> 3;        // 0..31
    const int ld_chk = tid & 7;
    const uint32_t doff = (uint32_t)(ld_row * 128 + ((ld_chk ^ (ld_row & 7)) << 4));
    const __half* xsrc = g_xq + (size_t)(m0 + ld_row) * K_TOTAL + ld_chk * 8;
    const __half* wsrc = g_w16 + (size_t)(n0 + ld_row) * K_TOTAL + ld_chk * 8;

    auto load_stage = [&](int s, int it) {
        uint32_t stb = sb + s * STAGE_BYTES;
        const __half* xs = xsrc + it * BK;
        const __half* ws = wsrc + it * BK;
#pragma unroll
        for (int j = 0; j < 4; ++j) {
            cp16(stb + OFF_X + doff + j * 4096, xs + (size_t)j * 32 * K_TOTAL);
            cp16(stb + OFF_W + doff + j * 4096, ws + (size_t)j * 32 * K_TOTAL);
        }
    };

#pragma unroll
    for (int s = 0; s < STAGES - 1; ++s) {
        load_stage(s, s);
        cp_commit();
    }

    float acc[4][4][4];
#pragma unroll
    for (int a = 0; a < 4; ++a)
#pragma unroll
        for (int b = 0; b < 4; ++b)
#pragma unroll
            for (int c = 0; c < 4; ++c) acc[a][b][c] = 0.0f;

    // A frags (non-trans): {m0-7,klo},{m8-15,klo},{m0-7,khi},{m8-15,khi}
    const int a_row_l = lane & 15;
    const int a_chk_l = lane >> 4;
    // B frags (non-trans, W rows = n): {n0-7,klo},{n0-7,khi},{n8-15,klo},{n8-15,khi}
    const int b_row_l = ((lane >> 4) << 3) + (lane & 7);
    const int b_chk_l = (lane >> 3) & 1;
    const int tr = lane >> 2;
    const int tc = (lane & 3) * 2;

    for (int it = 0; it < K_ITERS; ++it) {
        cp_wait<STAGES - 2>();
        __syncthreads();

        int nxt = it + STAGES - 1;
        if (nxt < K_ITERS) load_stage(nxt % STAGES, nxt);
        cp_commit();

        uint32_t stb = sb + (it % STAGES) * STAGE_BYTES;

#pragma unroll
        for (int kk = 0; kk < 4; ++kk) {
            uint32_t a[4][4], bq[2][4];
            // B first: first MMA operands ready after 3rd ldsm, not 5th
#pragma unroll
            for (int nb = 0; nb < 2; ++nb) {
                int row = warp_n * 32 + nb * 16 + b_row_l;
                ldsm_x4(bq[nb], tile_addr(stb + OFF_W, row, kk * 2 + b_chk_l));
            }
#pragma unroll
            for (int mt = 0; mt < 4; ++mt) {
                int row = warp_m * 64 + mt * 16 + a_row_l;
                ldsm_x4(a[mt], tile_addr(stb + OFF_X, row, kk * 2 + a_chk_l));
            }
#pragma unroll
            for (int mt = 0; mt < 4; ++mt)
#pragma unroll
                for (int nt = 0; nt < 4; ++nt) {
                    const int nb = nt >> 1;
                    const int hi = (nt & 1) * 2;
                    mma16816(acc[mt][nt], a[mt], bq[nb][hi], bq[nb][hi + 1]);
                }
        }
    }

    // ---- epilogue: LoRA (rank-16) + bias, then store ----
    cp_wait<0>();
    __syncthreads();
    float* xa_s = reinterpret_cast<float*>(smem);                // [128][17]
    float* bl_s = reinterpret_cast<float*>(smem + 128 * 17 * 4); // [16][128]
#pragma unroll
    for (int j = 0; j < 8; ++j) {
        int idx = tid + NTHREADS * j;      // 0..2047
        int row = idx >> 4, r = idx & 15;
        xa_s[row * 17 + r] = g_xa[(size_t)(m0 + row) * RANK + r];
        int rr = idx >> 7, col = idx & 127;
        bl_s[rr * 128 + col] = SCALING * loraB[(size_t)rr * N_TOTAL + n0 + col];
    }
    __syncthreads();

#pragma unroll
    for (int r = 0; r < RANK; ++r) {
        float xv[8];
#pragma unroll
        for (int mt = 0; mt < 4; ++mt) {
            int rowl = warp_m * 64 + mt * 16 + tr;
            xv[2 * mt]     = xa_s[rowl * 17 + r];
            xv[2 * mt + 1] = xa_s[(rowl + 8) * 17 + r];
        }
#pragma unroll
        for (int nt = 0; nt < 4; ++nt) {
            float2 bv = *reinterpret_cast<const float2*>(
                &bl_s[r * 128 + warp_n * 32 + nt * 8 + tc]);
#pragma unroll
            for (int mt = 0; mt < 4; ++mt) {
                acc[mt][nt][0] = fmaf(xv[2 * mt],     bv.x, acc[mt][nt][0]);
                acc[mt][nt][1] = fmaf(xv[2 * mt],     bv.y, acc[mt][nt][1]);
                acc[mt][nt][2] = fmaf(xv[2 * mt + 1], bv.x, acc[mt][nt][2]);
                acc[mt][nt][3] = fmaf(xv[2 * mt + 1], bv.y, acc[mt][nt][3]);
            }
        }
    }

#pragma unroll
    for (int nt = 0; nt < 4; ++nt) {
        int n = n0 + warp_n * 32 + nt * 8 + tc;
        float2 bv = *reinterpret_cast<const float2*>(bias + n);
#pragma unroll
        for (int mt = 0; mt < 4; ++mt) {
            int m = m0 + warp_m * 64 + mt * 16 + tr;
            float2 v0 = make_float2(acc[mt][nt][0] + bv.x, acc[mt][nt][1] + bv.y);
            float2 v1 = make_float2(acc[mt][nt][2] + bv.x, acc[mt][nt][3] + bv.y);
            *reinterpret_cast<float2*>(out + (size_t)m * N_TOTAL + n) = v0;
            *reinterpret_cast<float2*>(out + (size_t)(m + 8) * N_TOTAL + n) = v1;
        }
    }
}

// ---------------- host launch ----------------
extern "C" void kernel_launch(void* const* d_in, const int* in_sizes, int n_in,
                              void* d_out, int out_size) {
    const float* x      = (const float*)d_in[0];
    const int*   qw     = (const int*)d_in[1];
    const float* scales = (const float*)d_in[2];
    const float* bias   = (const float*)d_in[3];
    const float* lora_A = (const float*)d_in[4];
    const float* lora_B = (const float*)d_in[5];
    float* out = (float*)d_out;

    {
        size_t w16 = (size_t)N_TOTAL * K_TOTAL / 16;
        prep_w_kernel<<<(unsigned)((w16 + 255) / 256), 256>>>(qw, scales);
        prep_x_xa_kernel<<<M_TOTAL / 32, 256>>>(x, lora_A);
    }

    cudaFuncSetAttribute(gemm_kernel, cudaFuncAttributeMaxDynamicSharedMemorySize,
                         SMEM_BYTES);
    int grid = (M_TOTAL / BM) * (N_TOTAL / BN);   // 2048
    gemm_kernel<<<grid, NTHREADS, SMEM_BYTES>>>(bias, lora_B, out);
}